// round 1
// baseline (speedup 1.0000x reference)
#include <cuda_runtime.h>
#include <mma.h>
#include <cstdint>

using namespace nvcuda;

#define BATCH 4
#define SEQ   2048
#define DIM   1024
#define MROWS (BATCH * SEQ)                 // 8192
#define ATT_ELEMS ((size_t)BATCH * SEQ * SEQ)  // 16,777,216
#define LN_EPS 1e-5f

// ---------------------------------------------------------------------------
// Scratch (device-global: allocation inside kernel_launch is forbidden)
// ---------------------------------------------------------------------------
__device__ float g_xn[MROWS * DIM];
__device__ float g_q [MROWS * DIM];
__device__ float g_k [MROWS * DIM];
__device__ float g_v [MROWS * DIM];

// ---------------------------------------------------------------------------
// LayerNorm: one block per row of 1024 floats, 256 threads (float4 each)
// ---------------------------------------------------------------------------
__global__ __launch_bounds__(256) void ln_kernel(
    const float* __restrict__ x, const float* __restrict__ w,
    const float* __restrict__ b, float* __restrict__ out)
{
    int row = blockIdx.x;
    int t = threadIdx.x;
    const float4* xr = reinterpret_cast<const float4*>(x + (size_t)row * DIM);
    float4 v = xr[t];

    float s  = v.x + v.y + v.z + v.w;
    float s2 = v.x * v.x + v.y * v.y + v.z * v.z + v.w * v.w;

    __shared__ float red0[32], red1[32];
    #pragma unroll
    for (int o = 16; o > 0; o >>= 1) {
        s  += __shfl_xor_sync(0xFFFFFFFFu, s,  o);
        s2 += __shfl_xor_sync(0xFFFFFFFFu, s2, o);
    }
    int wid = t >> 5, lane = t & 31;
    if (lane == 0) { red0[wid] = s; red1[wid] = s2; }
    __syncthreads();
    if (wid == 0) {
        float a  = (lane < 8) ? red0[lane] : 0.0f;
        float a2 = (lane < 8) ? red1[lane] : 0.0f;
        #pragma unroll
        for (int o = 4; o > 0; o >>= 1) {
            a  += __shfl_xor_sync(0xFFFFFFFFu, a,  o);
            a2 += __shfl_xor_sync(0xFFFFFFFFu, a2, o);
        }
        if (lane == 0) { red0[0] = a * (1.0f / DIM); red1[0] = a2 * (1.0f / DIM); }
    }
    __syncthreads();
    float mu  = red0[0];
    float var = red1[0] - mu * mu;
    float inv = rsqrtf(var + LN_EPS);

    float4 w4 = reinterpret_cast<const float4*>(w)[t];
    float4 b4 = reinterpret_cast<const float4*>(b)[t];
    float4 o4;
    o4.x = (v.x - mu) * inv * w4.x + b4.x;
    o4.y = (v.y - mu) * inv * w4.y + b4.y;
    o4.z = (v.z - mu) * inv * w4.z + b4.z;
    o4.w = (v.w - mu) * inv * w4.w + b4.w;
    reinterpret_cast<float4*>(out + (size_t)row * DIM)[t] = o4;
}

// ---------------------------------------------------------------------------
// TF32 WMMA GEMM: C = scale * (A @ B) + bias
//   A: [M,K] row-major (lda)
//   B: BT=false -> [K,N] row-major (ldb);  BT=true -> [N,K] row-major (ldb),
//      i.e. C = A @ B^T
//   Batched via blockIdx.z with element strides sA/sB/sC.
//   Block tile 128x128, BK=16, 256 threads (8 warps, 2x4), warp tile 64x32.
//   All dims assumed divisible by tiles (true for this problem).
// ---------------------------------------------------------------------------
template <bool BT>
__global__ __launch_bounds__(256) void gemm128_tf32(
    const float* __restrict__ A, const float* __restrict__ Bm,
    float* __restrict__ C, const float* __restrict__ bias,
    int K, int lda, int ldb, int ldc, float scale,
    long long sA, long long sB, long long sC)
{
    constexpr int BM = 128, BN = 128, BK = 16;
    __shared__ float As[BM * BK];      // row-major, ld = BK
    __shared__ float Bs[BN * BK > BK * BN ? BN * BK : BK * BN]; // 2048 floats either way
    __shared__ float Cs[8][16 * 16];

    const float* Ab = A  + blockIdx.z * sA;
    const float* Bb = Bm + blockIdx.z * sB;
    float*       Cb = C  + blockIdx.z * sC;

    int tid  = threadIdx.x;
    int wid  = tid >> 5, lane = tid & 31;
    int warpM = wid >> 2;   // 0..1  (64 rows each)
    int warpN = wid & 3;    // 0..3  (32 cols each)
    int bm = blockIdx.y * BM;
    int bn = blockIdx.x * BN;

    wmma::fragment<wmma::accumulator, 16, 16, 8, float> acc[4][2];
    #pragma unroll
    for (int mi = 0; mi < 4; mi++)
        #pragma unroll
        for (int ni = 0; ni < 2; ni++)
            wmma::fill_fragment(acc[mi][ni], 0.0f);

    for (int k0 = 0; k0 < K; k0 += BK) {
        // Load A tile: 128 rows x 16 cols = 512 float4 slots
        #pragma unroll
        for (int p = 0; p < 2; p++) {
            int slot = tid + p * 256;
            int r = slot >> 2, cseg = slot & 3;
            float4 val = *reinterpret_cast<const float4*>(
                Ab + (size_t)(bm + r) * lda + k0 + cseg * 4);
            *reinterpret_cast<float4*>(As + r * BK + cseg * 4) = val;
        }
        if constexpr (!BT) {
            // B tile: 16 rows x 128 cols, row-major ld = BN
            #pragma unroll
            for (int p = 0; p < 2; p++) {
                int slot = tid + p * 256;
                int r = slot >> 5, cs = slot & 31;
                float4 val = *reinterpret_cast<const float4*>(
                    Bb + (size_t)(k0 + r) * ldb + bn + cs * 4);
                *reinterpret_cast<float4*>(Bs + r * BN + cs * 4) = val;
            }
        } else {
            // B tile: 128 n-rows x 16 k-cols -> col-major tile (element (k,n) at n*BK+k)
            #pragma unroll
            for (int p = 0; p < 2; p++) {
                int slot = tid + p * 256;
                int n = slot >> 2, kseg = slot & 3;
                float4 val = *reinterpret_cast<const float4*>(
                    Bb + (size_t)(bn + n) * ldb + k0 + kseg * 4);
                *reinterpret_cast<float4*>(Bs + n * BK + kseg * 4) = val;
            }
        }
        __syncthreads();

        #pragma unroll
        for (int kk = 0; kk < BK; kk += 8) {
            wmma::fragment<wmma::matrix_a, 16, 16, 8, wmma::precision::tf32,
                           wmma::row_major> af[4];
            #pragma unroll
            for (int mi = 0; mi < 4; mi++) {
                wmma::load_matrix_sync(af[mi],
                    As + (warpM * 64 + mi * 16) * BK + kk, BK);
                #pragma unroll
                for (int i = 0; i < af[mi].num_elements; i++)
                    af[mi].x[i] = wmma::__float_to_tf32(af[mi].x[i]);
            }
            if constexpr (!BT) {
                wmma::fragment<wmma::matrix_b, 16, 16, 8, wmma::precision::tf32,
                               wmma::row_major> bf[2];
                #pragma unroll
                for (int ni = 0; ni < 2; ni++) {
                    wmma::load_matrix_sync(bf[ni],
                        Bs + kk * BN + warpN * 32 + ni * 16, BN);
                    #pragma unroll
                    for (int i = 0; i < bf[ni].num_elements; i++)
                        bf[ni].x[i] = wmma::__float_to_tf32(bf[ni].x[i]);
                }
                #pragma unroll
                for (int mi = 0; mi < 4; mi++)
                    #pragma unroll
                    for (int ni = 0; ni < 2; ni++)
                        wmma::mma_sync(acc[mi][ni], af[mi], bf[ni], acc[mi][ni]);
            } else {
                wmma::fragment<wmma::matrix_b, 16, 16, 8, wmma::precision::tf32,
                               wmma::col_major> bf[2];
                #pragma unroll
                for (int ni = 0; ni < 2; ni++) {
                    wmma::load_matrix_sync(bf[ni],
                        Bs + (warpN * 32 + ni * 16) * BK + kk, BK);
                    #pragma unroll
                    for (int i = 0; i < bf[ni].num_elements; i++)
                        bf[ni].x[i] = wmma::__float_to_tf32(bf[ni].x[i]);
                }
                #pragma unroll
                for (int mi = 0; mi < 4; mi++)
                    #pragma unroll
                    for (int ni = 0; ni < 2; ni++)
                        wmma::mma_sync(acc[mi][ni], af[mi], bf[ni], acc[mi][ni]);
            }
        }
        __syncthreads();
    }

    // Epilogue: stage each 16x16 frag through smem, apply scale + bias
    #pragma unroll
    for (int mi = 0; mi < 4; mi++) {
        #pragma unroll
        for (int ni = 0; ni < 2; ni++) {
            wmma::store_matrix_sync(&Cs[wid][0], acc[mi][ni], 16,
                                    wmma::mem_row_major);
            __syncwarp();
            int r0 = bm + warpM * 64 + mi * 16;
            int c0 = bn + warpN * 32 + ni * 16;
            #pragma unroll
            for (int e = 0; e < 8; e++) {
                int idx = lane * 8 + e;
                int rr = idx >> 4, cc = idx & 15;
                float val = Cs[wid][idx] * scale;
                if (bias) val += bias[c0 + cc];
                Cb[(size_t)(r0 + rr) * ldc + c0 + cc] = val;
            }
            __syncwarp();
        }
    }
}

// ---------------------------------------------------------------------------
// Row softmax over rows of length SEQ=2048, in place. One block per row.
// ---------------------------------------------------------------------------
__global__ __launch_bounds__(256) void softmax_kernel(float* __restrict__ att)
{
    int row = blockIdx.x;
    float* p = att + (size_t)row * SEQ;
    int t = threadIdx.x;

    float4 v0 = reinterpret_cast<float4*>(p)[t];
    float4 v1 = reinterpret_cast<float4*>(p)[t + 256];

    float m = fmaxf(fmaxf(fmaxf(v0.x, v0.y), fmaxf(v0.z, v0.w)),
                    fmaxf(fmaxf(v1.x, v1.y), fmaxf(v1.z, v1.w)));

    __shared__ float red[32];
    #pragma unroll
    for (int o = 16; o > 0; o >>= 1)
        m = fmaxf(m, __shfl_xor_sync(0xFFFFFFFFu, m, o));
    int wid = t >> 5, lane = t & 31;
    if (lane == 0) red[wid] = m;
    __syncthreads();
    if (wid == 0) {
        float a = (lane < 8) ? red[lane] : -3.4e38f;
        #pragma unroll
        for (int o = 4; o > 0; o >>= 1)
            a = fmaxf(a, __shfl_xor_sync(0xFFFFFFFFu, a, o));
        if (lane == 0) red[0] = a;
    }
    __syncthreads();
    m = red[0];

    v0.x = expf(v0.x - m); v0.y = expf(v0.y - m);
    v0.z = expf(v0.z - m); v0.w = expf(v0.w - m);
    v1.x = expf(v1.x - m); v1.y = expf(v1.y - m);
    v1.z = expf(v1.z - m); v1.w = expf(v1.w - m);

    float s = v0.x + v0.y + v0.z + v0.w + v1.x + v1.y + v1.z + v1.w;
    #pragma unroll
    for (int o = 16; o > 0; o >>= 1)
        s += __shfl_xor_sync(0xFFFFFFFFu, s, o);
    if (lane == 0) red[wid] = s;
    __syncthreads();
    if (wid == 0) {
        float a = (lane < 8) ? red[lane] : 0.0f;
        #pragma unroll
        for (int o = 4; o > 0; o >>= 1)
            a += __shfl_xor_sync(0xFFFFFFFFu, a, o);
        if (lane == 0) red[0] = a;
    }
    __syncthreads();
    float inv = 1.0f / red[0];

    v0.x *= inv; v0.y *= inv; v0.z *= inv; v0.w *= inv;
    v1.x *= inv; v1.y *= inv; v1.z *= inv; v1.w *= inv;
    reinterpret_cast<float4*>(p)[t]       = v0;
    reinterpret_cast<float4*>(p)[t + 256] = v1;
}

// ---------------------------------------------------------------------------
// Launch
// ---------------------------------------------------------------------------
extern "C" void kernel_launch(void* const* d_in, const int* in_sizes, int n_in,
                              void* d_out, int out_size)
{
    (void)in_sizes; (void)n_in; (void)out_size;
    const float* x   = (const float*)d_in[0];
    const float* wq  = (const float*)d_in[1];
    const float* bq  = (const float*)d_in[2];
    const float* wk  = (const float*)d_in[3];
    const float* bk  = (const float*)d_in[4];
    const float* wv  = (const float*)d_in[5];
    const float* bv  = (const float*)d_in[6];
    const float* lnw = (const float*)d_in[7];
    const float* lnb = (const float*)d_in[8];

    float* att = (float*)d_out;                 // [4,2048,2048]
    float* out = att + ATT_ELEMS;               // [4,2048,1024]

    float *xn, *q, *k, *v;
    cudaGetSymbolAddress((void**)&xn, g_xn);
    cudaGetSymbolAddress((void**)&q,  g_q);
    cudaGetSymbolAddress((void**)&k,  g_k);
    cudaGetSymbolAddress((void**)&v,  g_v);

    // 1) LayerNorm
    ln_kernel<<<MROWS, 256>>>(x, lnw, lnb, xn);

    // 2) Q/K/V projections: [8192,1024] @ [1024,1024] + bias
    dim3 gQKV(DIM / 128, MROWS / 128, 1);
    gemm128_tf32<false><<<gQKV, 256>>>(xn, wq, q, bq, DIM, DIM, DIM, DIM, 1.0f, 0, 0, 0);
    gemm128_tf32<false><<<gQKV, 256>>>(xn, wk, k, bk, DIM, DIM, DIM, DIM, 1.0f, 0, 0, 0);
    gemm128_tf32<false><<<gQKV, 256>>>(xn, wv, v, bv, DIM, DIM, DIM, DIM, 1.0f, 0, 0, 0);

    // 3) Scores: att[b] = (q[b] @ k[b]^T) / 32, batched over 4
    dim3 gS(SEQ / 128, SEQ / 128, BATCH);
    gemm128_tf32<true><<<gS, 256>>>(q, k, att, nullptr, DIM, DIM, DIM, SEQ,
                                    1.0f / 32.0f,
                                    (long long)SEQ * DIM, (long long)SEQ * DIM,
                                    (long long)SEQ * SEQ);

    // 4) Softmax (in place in d_out)
    softmax_kernel<<<MROWS, 256>>>(att);

    // 5) out[b] = att[b] @ v[b]
    dim3 gO(DIM / 128, SEQ / 128, BATCH);
    gemm128_tf32<false><<<gO, 256>>>(att, v, out, nullptr, SEQ, SEQ, DIM, DIM,
                                     1.0f,
                                     (long long)SEQ * SEQ, (long long)SEQ * DIM,
                                     (long long)SEQ * DIM);
}

// round 2
// speedup vs baseline: 1.3482x; 1.3482x over previous
#include <cuda_runtime.h>
#include <mma.h>
#include <cstdint>

using namespace nvcuda;

#define BATCH 4
#define SEQ   2048
#define DIM   1024
#define MROWS (BATCH * SEQ)                    // 8192
#define ATT_ELEMS ((size_t)BATCH * SEQ * SEQ)  // 16,777,216
#define LN_EPS 1e-5f

// ---------------------------------------------------------------------------
// Scratch (device globals: no allocation allowed in kernel_launch)
// ---------------------------------------------------------------------------
__device__ float g_xn[MROWS * DIM];
__device__ float g_q [MROWS * DIM];
__device__ float g_k [MROWS * DIM];
__device__ float g_v [MROWS * DIM];
__device__ float g_wr[3][DIM * DIM];   // tf32-rounded weights

// ---------------------------------------------------------------------------
// Helpers
// ---------------------------------------------------------------------------
__device__ __forceinline__ float rtf32(float x) {
    return wmma::__float_to_tf32(x);   // cvt.rna.tf32.f32 (value-preserving for mma)
}

__device__ __forceinline__ void cp16(void* smem, const void* gmem) {
    uint32_t s = (uint32_t)__cvta_generic_to_shared(smem);
    asm volatile("cp.async.cg.shared.global [%0], [%1], 16;\n" :: "r"(s), "l"(gmem));
}
#define CP_COMMIT() asm volatile("cp.async.commit_group;\n")
#define CP_WAIT1()  asm volatile("cp.async.wait_group 1;\n")
#define CP_WAIT0()  asm volatile("cp.async.wait_group 0;\n")

// ---------------------------------------------------------------------------
// Weight pre-rounding to tf32 (removes per-fragment cvt from GEMM mainloop)
// ---------------------------------------------------------------------------
__global__ __launch_bounds__(256) void round_w_kernel(
    const float* __restrict__ w0, const float* __restrict__ w1,
    const float* __restrict__ w2)
{
    int z = blockIdx.y;
    const float* src = (z == 0) ? w0 : (z == 1) ? w1 : w2;
    float* dst = g_wr[z];
    int i = (blockIdx.x * 256 + threadIdx.x) * 4;
    float4 v = *reinterpret_cast<const float4*>(src + i);
    v.x = rtf32(v.x); v.y = rtf32(v.y); v.z = rtf32(v.z); v.w = rtf32(v.w);
    *reinterpret_cast<float4*>(dst + i) = v;
}

// ---------------------------------------------------------------------------
// LayerNorm: one block per row of 1024 floats, output pre-rounded to tf32
// ---------------------------------------------------------------------------
__global__ __launch_bounds__(256) void ln_kernel(
    const float* __restrict__ x, const float* __restrict__ w,
    const float* __restrict__ b, float* __restrict__ out)
{
    int row = blockIdx.x;
    int t = threadIdx.x;
    const float4* xr = reinterpret_cast<const float4*>(x + (size_t)row * DIM);
    float4 v = xr[t];

    float s  = v.x + v.y + v.z + v.w;
    float s2 = v.x * v.x + v.y * v.y + v.z * v.z + v.w * v.w;

    __shared__ float red0[32], red1[32];
    #pragma unroll
    for (int o = 16; o > 0; o >>= 1) {
        s  += __shfl_xor_sync(0xFFFFFFFFu, s,  o);
        s2 += __shfl_xor_sync(0xFFFFFFFFu, s2, o);
    }
    int wid = t >> 5, lane = t & 31;
    if (lane == 0) { red0[wid] = s; red1[wid] = s2; }
    __syncthreads();
    if (wid == 0) {
        float a  = (lane < 8) ? red0[lane] : 0.0f;
        float a2 = (lane < 8) ? red1[lane] : 0.0f;
        #pragma unroll
        for (int o = 4; o > 0; o >>= 1) {
            a  += __shfl_xor_sync(0xFFFFFFFFu, a,  o);
            a2 += __shfl_xor_sync(0xFFFFFFFFu, a2, o);
        }
        if (lane == 0) { red0[0] = a * (1.0f / DIM); red1[0] = a2 * (1.0f / DIM); }
    }
    __syncthreads();
    float mu  = red0[0];
    float var = red1[0] - mu * mu;
    float inv = rsqrtf(var + LN_EPS);

    float4 w4 = reinterpret_cast<const float4*>(w)[t];
    float4 b4 = reinterpret_cast<const float4*>(b)[t];
    float4 o4;
    o4.x = rtf32((v.x - mu) * inv * w4.x + b4.x);
    o4.y = rtf32((v.y - mu) * inv * w4.y + b4.y);
    o4.z = rtf32((v.z - mu) * inv * w4.z + b4.z);
    o4.w = rtf32((v.w - mu) * inv * w4.w + b4.w);
    reinterpret_cast<float4*>(out + (size_t)row * DIM)[t] = o4;
}

// ---------------------------------------------------------------------------
// Pipelined TF32 WMMA GEMM body. C = scale*(A@B or A@B^T) + bias
// Block tile 128x128x16, 2-stage cp.async double buffer, 256 threads,
// 8 warps in 2x4 grid, warp tile 64x32 (4x2 of 16x16).
// Inputs assumed pre-rounded to tf32 unless CVT_A.
// ---------------------------------------------------------------------------
template <bool BT, bool CVT_A, bool ROUND_OUT>
__device__ __forceinline__ void gemm_body(
    const float* __restrict__ Ab, const float* __restrict__ Bb,
    float* __restrict__ Cb, const float* __restrict__ bias,
    int K, int lda, int ldb, int ldc, float scale)
{
    constexpr int BM = 128, BN = 128, BK = 16;
    constexpr int LDA_S = 24;                    // padded (mult of 8)
    constexpr int LDB_S = BT ? 24 : 136;
    constexpr int ASZ = BM * LDA_S;              // 3072
    constexpr int BSZ = BT ? (BN * LDB_S) : (BK * LDB_S);

    __shared__ float As[2][ASZ];
    __shared__ float Bs[2][BSZ];

    int tid = threadIdx.x;
    int wid = tid >> 5, lane = tid & 31;
    int warpM = wid >> 2;   // 0..1
    int warpN = wid & 3;    // 0..3
    int bm = blockIdx.y * BM;
    int bn = blockIdx.x * BN;

    auto load_stage = [&](int s, int k0) {
        #pragma unroll
        for (int p = 0; p < 2; p++) {           // A: 128 x 16
            int slot = tid + p * 256;
            int r = slot >> 2, cs = slot & 3;
            cp16(&As[s][r * LDA_S + cs * 4],
                 Ab + (size_t)(bm + r) * lda + k0 + cs * 4);
        }
        if constexpr (!BT) {                    // B: 16 x 128 row-major
            #pragma unroll
            for (int p = 0; p < 2; p++) {
                int slot = tid + p * 256;
                int r = slot >> 5, cs = slot & 31;
                cp16(&Bs[s][r * LDB_S + cs * 4],
                     Bb + (size_t)(k0 + r) * ldb + bn + cs * 4);
            }
        } else {                                // B^T: 128 n-rows x 16 k-cols
            #pragma unroll
            for (int p = 0; p < 2; p++) {
                int slot = tid + p * 256;
                int n = slot >> 2, ks = slot & 3;
                cp16(&Bs[s][n * LDB_S + ks * 4],
                     Bb + (size_t)(bn + n) * ldb + k0 + ks * 4);
            }
        }
    };

    wmma::fragment<wmma::accumulator, 16, 16, 8, float> acc[4][2];
    #pragma unroll
    for (int mi = 0; mi < 4; mi++)
        #pragma unroll
        for (int ni = 0; ni < 2; ni++)
            wmma::fill_fragment(acc[mi][ni], 0.0f);

    int NT = K / BK;
    load_stage(0, 0);
    CP_COMMIT();

    for (int kt = 0; kt < NT; kt++) {
        int cur = kt & 1;
        if (kt + 1 < NT) {
            load_stage(cur ^ 1, (kt + 1) * BK);
            CP_COMMIT();
            CP_WAIT1();
        } else {
            CP_WAIT0();
        }
        __syncthreads();

        #pragma unroll
        for (int kk = 0; kk < BK; kk += 8) {
            wmma::fragment<wmma::matrix_a, 16, 16, 8, wmma::precision::tf32,
                           wmma::row_major> af[4];
            #pragma unroll
            for (int mi = 0; mi < 4; mi++) {
                wmma::load_matrix_sync(af[mi],
                    &As[cur][(warpM * 64 + mi * 16) * LDA_S + kk], LDA_S);
                if constexpr (CVT_A) {
                    #pragma unroll
                    for (int i = 0; i < af[mi].num_elements; i++)
                        af[mi].x[i] = rtf32(af[mi].x[i]);
                }
            }
            if constexpr (!BT) {
                wmma::fragment<wmma::matrix_b, 16, 16, 8, wmma::precision::tf32,
                               wmma::row_major> bf[2];
                #pragma unroll
                for (int ni = 0; ni < 2; ni++)
                    wmma::load_matrix_sync(bf[ni],
                        &Bs[cur][kk * LDB_S + warpN * 32 + ni * 16], LDB_S);
                #pragma unroll
                for (int mi = 0; mi < 4; mi++)
                    #pragma unroll
                    for (int ni = 0; ni < 2; ni++)
                        wmma::mma_sync(acc[mi][ni], af[mi], bf[ni], acc[mi][ni]);
            } else {
                wmma::fragment<wmma::matrix_b, 16, 16, 8, wmma::precision::tf32,
                               wmma::col_major> bf[2];
                #pragma unroll
                for (int ni = 0; ni < 2; ni++)
                    wmma::load_matrix_sync(bf[ni],
                        &Bs[cur][(warpN * 32 + ni * 16) * LDB_S + kk], LDB_S);
                #pragma unroll
                for (int mi = 0; mi < 4; mi++)
                    #pragma unroll
                    for (int ni = 0; ni < 2; ni++)
                        wmma::mma_sync(acc[mi][ni], af[mi], bf[ni], acc[mi][ni]);
            }
        }
        __syncthreads();
    }

    // Epilogue: stage through smem (reuse As), apply scale + bias (+round)
    float* stage = (float*)As + wid * 256;
    #pragma unroll
    for (int mi = 0; mi < 4; mi++) {
        #pragma unroll
        for (int ni = 0; ni < 2; ni++) {
            wmma::store_matrix_sync(stage, acc[mi][ni], 16, wmma::mem_row_major);
            __syncwarp();
            int r0 = bm + warpM * 64 + mi * 16;
            int c0 = bn + warpN * 32 + ni * 16;
            #pragma unroll
            for (int e = 0; e < 8; e++) {
                int idx = lane * 8 + e;
                int rr = idx >> 4, cc = idx & 15;
                float val = stage[idx] * scale;
                if (bias) val += bias[c0 + cc];
                if constexpr (ROUND_OUT) val = rtf32(val);
                Cb[(size_t)(r0 + rr) * ldc + c0 + cc] = val;
            }
            __syncwarp();
        }
    }
}

// ---------------------------------------------------------------------------
// GEMM kernel wrappers
// ---------------------------------------------------------------------------
__global__ __launch_bounds__(256) void qkv_kernel(
    const float* __restrict__ xn,
    const float* __restrict__ b0, const float* __restrict__ b1,
    const float* __restrict__ b2,
    float* q, float* k, float* v)
{
    int z = blockIdx.z;
    const float* B    = g_wr[z];
    const float* bias = (z == 0) ? b0 : (z == 1) ? b1 : b2;
    float* C          = (z == 0) ? q  : (z == 1) ? k  : v;
    gemm_body<false, false, true>(xn, B, C, bias, DIM, DIM, DIM, DIM, 1.0f);
}

__global__ __launch_bounds__(256) void scores_kernel(
    const float* __restrict__ q, const float* __restrict__ k,
    float* __restrict__ att)
{
    const float* Ab = q + (size_t)blockIdx.z * SEQ * DIM;
    const float* Bb = k + (size_t)blockIdx.z * SEQ * DIM;
    float* Cb = att + (size_t)blockIdx.z * SEQ * SEQ;
    gemm_body<true, false, false>(Ab, Bb, Cb, nullptr, DIM, DIM, DIM, SEQ,
                                  1.0f / 32.0f);
}

__global__ __launch_bounds__(256) void attv_kernel(
    const float* __restrict__ att, const float* __restrict__ v,
    float* __restrict__ out)
{
    const float* Ab = att + (size_t)blockIdx.z * SEQ * SEQ;
    const float* Bb = v + (size_t)blockIdx.z * SEQ * DIM;
    float* Cb = out + (size_t)blockIdx.z * SEQ * DIM;
    gemm_body<false, true, false>(Ab, Bb, Cb, nullptr, SEQ, SEQ, DIM, DIM, 1.0f);
}

// ---------------------------------------------------------------------------
// Row softmax over rows of length SEQ=2048, in place. One block per row.
// ---------------------------------------------------------------------------
__global__ __launch_bounds__(256) void softmax_kernel(float* __restrict__ att)
{
    int row = blockIdx.x;
    float* p = att + (size_t)row * SEQ;
    int t = threadIdx.x;

    float4 v0 = reinterpret_cast<float4*>(p)[t];
    float4 v1 = reinterpret_cast<float4*>(p)[t + 256];

    float m = fmaxf(fmaxf(fmaxf(v0.x, v0.y), fmaxf(v0.z, v0.w)),
                    fmaxf(fmaxf(v1.x, v1.y), fmaxf(v1.z, v1.w)));

    __shared__ float red[32];
    #pragma unroll
    for (int o = 16; o > 0; o >>= 1)
        m = fmaxf(m, __shfl_xor_sync(0xFFFFFFFFu, m, o));
    int wid = t >> 5, lane = t & 31;
    if (lane == 0) red[wid] = m;
    __syncthreads();
    if (wid == 0) {
        float a = (lane < 8) ? red[lane] : -3.4e38f;
        #pragma unroll
        for (int o = 4; o > 0; o >>= 1)
            a = fmaxf(a, __shfl_xor_sync(0xFFFFFFFFu, a, o));
        if (lane == 0) red[0] = a;
    }
    __syncthreads();
    m = red[0];

    v0.x = __expf(v0.x - m); v0.y = __expf(v0.y - m);
    v0.z = __expf(v0.z - m); v0.w = __expf(v0.w - m);
    v1.x = __expf(v1.x - m); v1.y = __expf(v1.y - m);
    v1.z = __expf(v1.z - m); v1.w = __expf(v1.w - m);

    float s = v0.x + v0.y + v0.z + v0.w + v1.x + v1.y + v1.z + v1.w;
    #pragma unroll
    for (int o = 16; o > 0; o >>= 1)
        s += __shfl_xor_sync(0xFFFFFFFFu, s, o);
    if (lane == 0) red[wid] = s;
    __syncthreads();
    if (wid == 0) {
        float a = (lane < 8) ? red[lane] : 0.0f;
        #pragma unroll
        for (int o = 4; o > 0; o >>= 1)
            a += __shfl_xor_sync(0xFFFFFFFFu, a, o);
        if (lane == 0) red[0] = a;
    }
    __syncthreads();
    float inv = 1.0f / red[0];

    v0.x *= inv; v0.y *= inv; v0.z *= inv; v0.w *= inv;
    v1.x *= inv; v1.y *= inv; v1.z *= inv; v1.w *= inv;
    reinterpret_cast<float4*>(p)[t]       = v0;
    reinterpret_cast<float4*>(p)[t + 256] = v1;
}

// ---------------------------------------------------------------------------
// Launch
// ---------------------------------------------------------------------------
extern "C" void kernel_launch(void* const* d_in, const int* in_sizes, int n_in,
                              void* d_out, int out_size)
{
    (void)in_sizes; (void)n_in; (void)out_size;
    const float* x   = (const float*)d_in[0];
    const float* wq  = (const float*)d_in[1];
    const float* bq  = (const float*)d_in[2];
    const float* wk  = (const float*)d_in[3];
    const float* bk  = (const float*)d_in[4];
    const float* wv  = (const float*)d_in[5];
    const float* bv  = (const float*)d_in[6];
    const float* lnw = (const float*)d_in[7];
    const float* lnb = (const float*)d_in[8];

    float* att = (float*)d_out;                 // [4,2048,2048]
    float* out = att + ATT_ELEMS;               // [4,2048,1024]

    float *xn, *q, *k, *v;
    cudaGetSymbolAddress((void**)&xn, g_xn);
    cudaGetSymbolAddress((void**)&q,  g_q);
    cudaGetSymbolAddress((void**)&k,  g_k);
    cudaGetSymbolAddress((void**)&v,  g_v);

    // 0) Round weights to tf32 once (3 x 1M elems)
    round_w_kernel<<<dim3(DIM * DIM / 1024, 3), 256>>>(wq, wk, wv);

    // 1) LayerNorm (outputs tf32-rounded)
    ln_kernel<<<MROWS, 256>>>(x, lnw, lnb, xn);

    // 2) Q/K/V projections in one launch: [8192,1024] @ [1024,1024] + bias
    qkv_kernel<<<dim3(DIM / 128, MROWS / 128, 3), 256>>>(xn, bq, bk, bv, q, k, v);

    // 3) Scores: att[b] = (q[b] @ k[b]^T) / 32
    scores_kernel<<<dim3(SEQ / 128, SEQ / 128, BATCH), 256>>>(q, k, att);

    // 4) Softmax (in place in d_out)
    softmax_kernel<<<MROWS, 256>>>(att);

    // 5) out[b] = att[b] @ v[b]
    attv_kernel<<<dim3(DIM / 128, SEQ / 128, BATCH), 256>>>(att, v, out);
}